// round 15
// baseline (speedup 1.0000x reference)
#include <cuda_runtime.h>
#include <cuda_bf16.h>
#include <math.h>

#define Bq   2
#define Lq   2048
#define Dq   512
#define Hq   8
#define Eq   64
#define Cq   64
#define NCq  (Lq / Cq)
#define BHq  (Bq * Hq)
#define Mrows (Bq * Lq)

// -------- scratch (device globals) --------
__device__ __align__(16) float g_q[BHq * Lq * Eq];
__device__ __align__(16) float g_k[BHq * Lq * Eq];
__device__ __align__(16) float g_v[BHq * Lq * Eq];
__device__ __align__(16) float g_M[BHq * NCq * Eq * Eq];
__device__ __align__(16) float g_P[BHq * NCq * Eq * Eq];
__device__ __align__(16) float g_ksum[BHq * NCq * Eq];
__device__ __align__(16) float g_psum[BHq * NCq * Eq];
__device__ __align__(16) float g_attn[Mrows * Dq];
__device__ __align__(16) float g_lin[Mrows * Dq];

// =================================================================
// GEMM1 (R9 core — FROZEN; adds n-tile offset for split launch):
// tile 64x96, 4x6. Full grid = 16 x 64 n/m tiles.
// =================================================================
__global__ __launch_bounds__(256)
void gemm_qkv_kernel(const float* __restrict__ X, const float* __restrict__ W,
                     const float* __restrict__ bias, int xoff) {
    const int K = 512, N = 1536;
    __shared__ __align__(16) float As[8][64];
    __shared__ __align__(16) float Bs[8][96];
    const int tid = threadIdx.x;
    const int m0 = blockIdx.y * 64;
    const int n0 = (blockIdx.x + xoff) * 96;

    const bool aAct = tid < 128;
    const int aRow = tid >> 1;
    const int aCol = (tid & 1) << 2;
    const bool bAct = (tid & 31) < 24;
    const int bRow = tid >> 5;
    const int bCol = (tid & 31) << 2;

    const float* Ag = X + (size_t)(m0 + aRow) * K + aCol;
    const float* Bg = W + (size_t)bRow * N + n0 + bCol;

    const int tm0 = (tid & 15) << 2;
    const int tn0 = (tid >> 4) * 6;

    float acc[4][6] = {};
    float4 aReg, bReg;
    if (aAct) aReg = *(const float4*)Ag;
    if (bAct) bReg = *(const float4*)Bg;

    for (int kt = 0; kt < K / 8; ++kt) {
        if (aAct) {
            As[aCol + 0][aRow] = aReg.x;
            As[aCol + 1][aRow] = aReg.y;
            As[aCol + 2][aRow] = aReg.z;
            As[aCol + 3][aRow] = aReg.w;
        }
        if (bAct) *(float4*)&Bs[bRow][bCol] = bReg;
        __syncthreads();
        if (kt + 1 < K / 8) {
            if (aAct) aReg = *(const float4*)(Ag + (kt + 1) * 8);
            if (bAct) bReg = *(const float4*)(Bg + (size_t)(kt + 1) * 8 * N);
        }
#pragma unroll
        for (int kk = 0; kk < 8; ++kk) {
            float4 a = *(const float4*)&As[kk][tm0];
            const float2* bp = (const float2*)&Bs[kk][tn0];
            float2 b01 = bp[0], b23 = bp[1], b45 = bp[2];
            float b[6] = {b01.x, b01.y, b23.x, b23.y, b45.x, b45.y};
            float av[4] = {a.x, a.y, a.z, a.w};
#pragma unroll
            for (int i = 0; i < 4; ++i)
#pragma unroll
                for (int j = 0; j < 6; ++j)
                    acc[i][j] += av[i] * b[j];
        }
        __syncthreads();
    }

    float bj[6];
#pragma unroll
    for (int j = 0; j < 6; ++j) bj[j] = bias[n0 + tn0 + j];
#pragma unroll
    for (int i = 0; i < 4; ++i) {
        int m = m0 + tm0 + i;
        int bb = m >> 11;
        int t  = m & 2047;
#pragma unroll
        for (int j = 0; j < 6; ++j) {
            int n = n0 + tn0 + j;
            float val = acc[i][j] + bj[j];
            int part = n >> 9;
            int r = n & 511;
            int h = r >> 6;
            int e = r & 63;
            size_t idx = (((size_t)(bb * Hq + h)) * Lq + t) * Eq + e;
            if (part == 0) {
                val = (val > 0.f ? val + 1.f : expf(val)) * 0.125f;
                g_q[idx] = val;
            } else if (part == 1) {
                val = (val > 0.f ? val + 1.f : expf(val));
                g_k[idx] = val;
            } else {
                g_v[idx] = val;
            }
        }
    }
}

// =================================================================
// GEMM2 (R14 verbatim — at floor): 32x64 tile, 64 threads, 8x4.
// =================================================================
__global__ __launch_bounds__(64)
void gemm_out_kernel(const float* __restrict__ W, const float* __restrict__ bias) {
    const int K = 512, N = 512;
    __shared__ __align__(16) float As[8][32];
    __shared__ __align__(16) float Bs[8][64];
    const int tid = threadIdx.x;
    const int m0 = blockIdx.y * 32;
    const int n0 = blockIdx.x * 64;

    const int aRow = tid >> 1;
    const int aCol = (tid & 1) << 2;
    const int bRow = tid >> 3;
    const int bCol = (tid & 7) << 3;

    const float* Ag = g_attn + (size_t)(m0 + aRow) * K + aCol;
    const float* Bg = W + (size_t)bRow * N + n0 + bCol;

    const int tm0 = (tid >> 4) << 3;
    const int tn0 = (tid & 15) << 2;

    float acc[8][4] = {};
    float4 aReg, bReg0, bReg1;
    aReg = *(const float4*)Ag;
    bReg0 = *(const float4*)Bg;
    bReg1 = *(const float4*)(Bg + 4);

    for (int kt = 0; kt < K / 8; ++kt) {
        As[aCol + 0][aRow] = aReg.x;
        As[aCol + 1][aRow] = aReg.y;
        As[aCol + 2][aRow] = aReg.z;
        As[aCol + 3][aRow] = aReg.w;
        *(float4*)&Bs[bRow][bCol] = bReg0;
        *(float4*)&Bs[bRow][bCol + 4] = bReg1;
        __syncthreads();
        if (kt + 1 < K / 8) {
            aReg = *(const float4*)(Ag + (kt + 1) * 8);
            bReg0 = *(const float4*)(Bg + (size_t)(kt + 1) * 8 * N);
            bReg1 = *(const float4*)(Bg + (size_t)(kt + 1) * 8 * N + 4);
        }
#pragma unroll
        for (int kk = 0; kk < 8; ++kk) {
            float4 a0 = *(const float4*)&As[kk][tm0];
            float4 a1 = *(const float4*)&As[kk][tm0 + 4];
            float4 b = *(const float4*)&Bs[kk][tn0];
            float av[8] = {a0.x, a0.y, a0.z, a0.w, a1.x, a1.y, a1.z, a1.w};
            float bv[4] = {b.x, b.y, b.z, b.w};
#pragma unroll
            for (int i = 0; i < 8; ++i)
#pragma unroll
                for (int j = 0; j < 4; ++j)
                    acc[i][j] += av[i] * bv[j];
        }
        __syncthreads();
    }

    float4 bb = *(const float4*)&bias[n0 + tn0];
#pragma unroll
    for (int i = 0; i < 8; ++i) {
        int m = m0 + tm0 + i;
        float4 v = make_float4(acc[i][0] + bb.x, acc[i][1] + bb.y,
                               acc[i][2] + bb.z, acc[i][3] + bb.w);
        *(float4*)(g_lin + (size_t)m * N + n0 + tn0) = v;
    }
}

// =================================================================
// K2: chunk summaries (R14 verbatim)
// =================================================================
__global__ __launch_bounds__(256)
void chunk_summary_kernel(const float* __restrict__ dlog) {
    __shared__ __align__(16) float Ks[4096];
    __shared__ __align__(16) float Vs[4096];
    __shared__ float lp[64];
    const int blk = blockIdx.x;
    const int bh = blk >> 5, c = blk & 31, h = bh & 7;
    const int tid = threadIdx.x;
    const float lam = 1.f / (1.f + expf(-dlog[h]));
    const float llog = logf(lam);
    const size_t off = ((size_t)bh * Lq + c * Cq) * Eq;
#pragma unroll
    for (int r = 0; r < 4; ++r) {
        int li = tid + 256 * r;
        ((float4*)Ks)[li] = ((const float4*)(g_k + off))[li];
        ((float4*)Vs)[li] = ((const float4*)(g_v + off))[li];
    }
    if (tid < 64) lp[tid] = expf((float)(63 - tid) * llog);
    __syncthreads();

    const int e = tid >> 2, f0 = (tid & 3) << 4;
    float acc[16] = {};
    float ks = 0.f;
    for (int j = 0; j < 64; ++j) {
        float kw = Ks[j * 64 + e] * lp[j];
        ks += kw;
#pragma unroll
        for (int ff = 0; ff < 16; ++ff) acc[ff] += kw * Vs[j * 64 + f0 + ff];
    }
    float* Mo = g_M + (size_t)blk * 4096 + e * 64 + f0;
#pragma unroll
    for (int ff = 0; ff < 16; ++ff) Mo[ff] = acc[ff];
    if ((tid & 3) == 0) g_ksum[blk * 64 + e] = ks;
}

// =================================================================
// K3 (R14 verbatim): 256 CTAs, 1 state element/thread.
// =================================================================
__global__ __launch_bounds__(256)
void state_scan_kernel(const float* __restrict__ dlog) {
    const int bh = blockIdx.y;
    const int grp = blockIdx.x;
    const int tid = threadIdx.x;
    const int h = bh & 7;
    const float lam = 1.f / (1.f + expf(-dlog[h]));
    const float lamC = expf(64.f * logf(lam));
    const int eidx = grp * 256 + tid;
    const bool doPsum = (grp == 0) && (tid < 64);

    float P = 0.f, ps = 0.f;
    for (int c = 0; c < 32; ++c) {
        size_t base = ((size_t)bh * 32 + c) * 4096 + eidx;
        float m = g_M[base];
        g_P[base] = P;
        P = lamC * P + m;
        if (doPsum) {
            int vi = (bh * 32 + c) * 64 + tid;
            float kv = g_ksum[vi];
            g_psum[vi] = ps;
            ps = lamC * ps + kv;
        }
    }
}

// =================================================================
// K4 (R14 verbatim): per-chunk output, Aw aliases Ks, AV early exit.
// =================================================================
#define K4_SMEM_FLOATS (4 * 64 * 64 + 64 + 68)

__device__ __forceinline__ int ksw(int row, int col) {
    return row * 64 + ((((col >> 2) ^ ((row >> 2) & 15)) << 2) | (col & 3));
}

__global__ __launch_bounds__(256)
void chunk_output_kernel(const float* __restrict__ dlog) {
    extern __shared__ float sm[];
    float* Qs = sm;
    float* Ks = sm + 64 * 64;
    float* Vs = sm + 2 * 64 * 64;
    float* Ps = sm + 3 * 64 * 64;
    float* Aw = Ks;
    float* pv = sm + 4 * 64 * 64;
    float* lp = pv + 64;

    const int blk = blockIdx.x, bh = blk >> 5, c = blk & 31;
    const int h = bh & 7, b = bh >> 3;
    const int tid = threadIdx.x;
    const float lam = 1.f / (1.f + expf(-dlog[h]));
    const float llog = logf(lam);

    const size_t chunk_off = ((size_t)bh * Lq + c * Cq) * Eq;
    const float4* q4 = (const float4*)(g_q + chunk_off);
    const float4* k4 = (const float4*)(g_k + chunk_off);
    const float4* v4 = (const float4*)(g_v + chunk_off);
    const float4* p4 = (const float4*)(g_P + (size_t)blk * 4096);
#pragma unroll
    for (int r = 0; r < 4; ++r) {
        int li = tid + 256 * r;
        ((float4*)Qs)[li] = q4[li];
        ((float4*)Vs)[li] = v4[li];
        ((float4*)Ps)[li] = p4[li];
        int fe = li << 2;
        int row = fe >> 6, col = fe & 63;
        *(float4*)&Ks[ksw(row, col)] = k4[li];
    }
    if (tid < 64) pv[tid] = g_psum[blk * 64 + tid];
    if (tid < 65) lp[tid] = expf((float)tid * llog);
    __syncthreads();

    const int jb = (tid >> 4) << 2;
    const int fb = (tid & 15) << 2;

    float acc2[4][4] = {};
    for (int e0 = 0; e0 < 64; e0 += 4) {
        float4 qv[4], kv[4];
#pragma unroll
        for (int a = 0; a < 4; ++a) qv[a] = *(const float4*)&Qs[(jb + a) * 64 + e0];
#pragma unroll
        for (int d = 0; d < 4; ++d) kv[d] = *(const float4*)&Ks[ksw(fb + d, e0)];
#pragma unroll
        for (int a = 0; a < 4; ++a)
#pragma unroll
            for (int d = 0; d < 4; ++d)
                acc2[a][d] += qv[a].x * kv[d].x + qv[a].y * kv[d].y
                            + qv[a].z * kv[d].z + qv[a].w * kv[d].w;
    }
    __syncthreads();
#pragma unroll
    for (int a = 0; a < 4; ++a) {
        int j = jb + a;
        float4 w4;
        w4.x = (fb + 0 <= j) ? acc2[a][0] * lp[j - fb - 0] : 0.f;
        w4.y = (fb + 1 <= j) ? acc2[a][1] * lp[j - fb - 1] : 0.f;
        w4.z = (fb + 2 <= j) ? acc2[a][2] * lp[j - fb - 2] : 0.f;
        w4.w = (fb + 3 <= j) ? acc2[a][3] * lp[j - fb - 3] : 0.f;
        *(float4*)&Aw[j * 64 + fb] = w4;
    }
    __syncthreads();

    float4 o4[4] = {}, po4[4] = {};
    float dsum[4] = {}, dq[4] = {};
    for (int i0 = 0; i0 <= jb + 3; i0 += 4) {
        float4 av[4], vv[4];
#pragma unroll
        for (int a = 0; a < 4; ++a) av[a] = *(const float4*)&Aw[(jb + a) * 64 + i0];
#pragma unroll
        for (int d = 0; d < 4; ++d) vv[d] = *(const float4*)&Vs[(i0 + d) * 64 + fb];
#pragma unroll
        for (int a = 0; a < 4; ++a) {
            dsum[a] += av[a].x + av[a].y + av[a].z + av[a].w;
            o4[a].x += av[a].x * vv[0].x + av[a].y * vv[1].x + av[a].z * vv[2].x + av[a].w * vv[3].x;
            o4[a].y += av[a].x * vv[0].y + av[a].y * vv[1].y + av[a].z * vv[2].y + av[a].w * vv[3].y;
            o4[a].z += av[a].x * vv[0].z + av[a].y * vv[1].z + av[a].z * vv[2].z + av[a].w * vv[3].z;
            o4[a].w += av[a].x * vv[0].w + av[a].y * vv[1].w + av[a].z * vv[2].w + av[a].w * vv[3].w;
        }
    }
    for (int e0 = 0; e0 < 64; e0 += 4) {
        float4 qv[4], pw[4];
#pragma unroll
        for (int a = 0; a < 4; ++a) qv[a] = *(const float4*)&Qs[(jb + a) * 64 + e0];
#pragma unroll
        for (int d = 0; d < 4; ++d) pw[d] = *(const float4*)&Ps[(e0 + d) * 64 + fb];
        float4 pvv = *(const float4*)&pv[e0];
#pragma unroll
        for (int a = 0; a < 4; ++a) {
            dq[a] += qv[a].x * pvv.x + qv[a].y * pvv.y + qv[a].z * pvv.z + qv[a].w * pvv.w;
            po4[a].x += qv[a].x * pw[0].x + qv[a].y * pw[1].x + qv[a].z * pw[2].x + qv[a].w * pw[3].x;
            po4[a].y += qv[a].x * pw[0].y + qv[a].y * pw[1].y + qv[a].z * pw[2].y + qv[a].w * pw[3].y;
            po4[a].z += qv[a].x * pw[0].z + qv[a].y * pw[1].z + qv[a].z * pw[2].z + qv[a].w * pw[3].z;
            po4[a].w += qv[a].x * pw[0].w + qv[a].y * pw[1].w + qv[a].z * pw[2].w + qv[a].w * pw[3].w;
        }
    }

#pragma unroll
    for (int a = 0; a < 4; ++a) {
        int j = jb + a;
        float l1 = lp[j + 1];
        float inv = 1.f / (dsum[a] + l1 * dq[a] + 1e-5f);
        int t = c * Cq + j;
        float4 res;
        res.x = (o4[a].x + l1 * po4[a].x) * inv;
        res.y = (o4[a].y + l1 * po4[a].y) * inv;
        res.z = (o4[a].z + l1 * po4[a].z) * inv;
        res.w = (o4[a].w + l1 * po4[a].w) * inv;
        *(float4*)(g_attn + ((size_t)(b * Lq + t)) * Dq + h * Eq + fb) = res;
    }
}

// =================================================================
// K6: LayerNorm (R14 verbatim)
// =================================================================
__global__ __launch_bounds__(128)
void ln_kernel(const float* __restrict__ gamma, const float* __restrict__ beta,
               float* __restrict__ out) {
    const int row = blockIdx.x, tid = threadIdx.x;
    float4 v = ((const float4*)(g_lin + (size_t)row * Dq))[tid];
    float s = v.x + v.y + v.z + v.w;
    float ss = v.x * v.x + v.y * v.y + v.z * v.z + v.w * v.w;
#pragma unroll
    for (int o = 16; o; o >>= 1) {
        s  += __shfl_xor_sync(0xffffffffu, s, o);
        ss += __shfl_xor_sync(0xffffffffu, ss, o);
    }
    __shared__ float rs[4], rss[4];
    if ((tid & 31) == 0) { rs[tid >> 5] = s; rss[tid >> 5] = ss; }
    __syncthreads();
    s = rs[0] + rs[1] + rs[2] + rs[3];
    ss = rss[0] + rss[1] + rss[2] + rss[3];
    const float mean = s * (1.f / 512.f);
    const float var = ss * (1.f / 512.f) - mean * mean;
    const float inv = rsqrtf(var + 1e-5f);
    float4 g = ((const float4*)gamma)[tid];
    float4 be = ((const float4*)beta)[tid];
    float4 o4;
    o4.x = (v.x - mean) * inv * g.x + be.x;
    o4.y = (v.y - mean) * inv * g.y + be.y;
    o4.z = (v.z - mean) * inv * g.z + be.z;
    o4.w = (v.w - mean) * inv * g.w + be.w;
    ((float4*)(out + (size_t)row * Dq))[tid] = o4;
}

// =================================================================
extern "C" void kernel_launch(void* const* d_in, const int* in_sizes, int n_in,
                              void* d_out, int out_size) {
    const float* x     = (const float*)d_in[0];
    const float* Wqkv  = (const float*)d_in[1];
    const float* bqkv  = (const float*)d_in[2];
    const float* Wout  = (const float*)d_in[3];
    const float* bout  = (const float*)d_in[4];
    const float* gamma = (const float*)d_in[5];
    const float* beta  = (const float*)d_in[6];
    const float* dlog  = (const float*)d_in[7];
    float* out = (float*)d_out;

    // One-time helper objects (host-side; identical GPU work every call).
    static cudaStream_t s2 = nullptr;
    static cudaEvent_t evA = nullptr, evB = nullptr;
    if (s2 == nullptr) {
        cudaStreamCreateWithFlags(&s2, cudaStreamNonBlocking);
        cudaEventCreateWithFlags(&evA, cudaEventDisableTiming);
        cudaEventCreateWithFlags(&evB, cudaEventDisableTiming);
    }

    cudaFuncSetAttribute(chunk_output_kernel,
                         cudaFuncAttributeMaxDynamicSharedMemorySize,
                         K4_SMEM_FLOATS * sizeof(float));

    // GEMM1a: n-tiles 5..15 (covers all k and v columns).
    gemm_qkv_kernel<<<dim3(11, 64), 256>>>(x, Wqkv, bqkv, 5);
    cudaEventRecord(evA, 0);

    // GEMM1b: n-tiles 0..4 (pure q) — runs while K2/K3 execute on s2.
    gemm_qkv_kernel<<<dim3(5, 64), 256>>>(x, Wqkv, bqkv, 0);

    // Side stream: chunk summaries + state scan (need only k,v).
    cudaStreamWaitEvent(s2, evA, 0);
    chunk_summary_kernel<<<BHq * NCq, 256, 0, s2>>>(dlog);
    state_scan_kernel<<<dim3(16, 16), 256, 0, s2>>>(dlog);
    cudaEventRecord(evB, s2);

    // Join: K4 needs q (stream 0) and P/psum (s2).
    cudaStreamWaitEvent(0, evB, 0);
    chunk_output_kernel<<<BHq * NCq, 256, K4_SMEM_FLOATS * sizeof(float)>>>(dlog);

    gemm_out_kernel<<<dim3(8, 128), 64>>>(Wout, bout);

    ln_kernel<<<Mrows, 128>>>(gamma, beta, out);
}

// round 16
// speedup vs baseline: 1.0531x; 1.0531x over previous
#include <cuda_runtime.h>
#include <cuda_bf16.h>
#include <math.h>

#define Bq   2
#define Lq   2048
#define Dq   512
#define Hq   8
#define Eq   64
#define Cq   64
#define NCq  (Lq / Cq)
#define BHq  (Bq * Hq)
#define Mrows (Bq * Lq)

// -------- scratch (device globals) --------
__device__ __align__(16) float g_q[BHq * Lq * Eq];
__device__ __align__(16) float g_k[BHq * Lq * Eq];
__device__ __align__(16) float g_v[BHq * Lq * Eq];
__device__ __align__(16) float g_M[BHq * NCq * Eq * Eq];
__device__ __align__(16) float g_P[BHq * NCq * Eq * Eq];
__device__ __align__(16) float g_ksum[BHq * NCq * Eq];
__device__ __align__(16) float g_psum[BHq * NCq * Eq];
__device__ __align__(16) float g_attn[Mrows * Dq];
__device__ __align__(16) float g_lin[Mrows * Dq];

// =================================================================
// GEMM1 (R9 core — FROZEN): tile 64x96, 4x6, grid 16x64.
// =================================================================
__global__ __launch_bounds__(256)
void gemm_qkv_kernel(const float* __restrict__ X, const float* __restrict__ W,
                     const float* __restrict__ bias) {
    const int K = 512, N = 1536;
    __shared__ __align__(16) float As[8][64];
    __shared__ __align__(16) float Bs[8][96];
    const int tid = threadIdx.x;
    const int m0 = blockIdx.y * 64;
    const int n0 = blockIdx.x * 96;

    const bool aAct = tid < 128;
    const int aRow = tid >> 1;
    const int aCol = (tid & 1) << 2;
    const bool bAct = (tid & 31) < 24;
    const int bRow = tid >> 5;
    const int bCol = (tid & 31) << 2;

    const float* Ag = X + (size_t)(m0 + aRow) * K + aCol;
    const float* Bg = W + (size_t)bRow * N + n0 + bCol;

    const int tm0 = (tid & 15) << 2;
    const int tn0 = (tid >> 4) * 6;

    float acc[4][6] = {};
    float4 aReg, bReg;
    if (aAct) aReg = *(const float4*)Ag;
    if (bAct) bReg = *(const float4*)Bg;

    for (int kt = 0; kt < K / 8; ++kt) {
        if (aAct) {
            As[aCol + 0][aRow] = aReg.x;
            As[aCol + 1][aRow] = aReg.y;
            As[aCol + 2][aRow] = aReg.z;
            As[aCol + 3][aRow] = aReg.w;
        }
        if (bAct) *(float4*)&Bs[bRow][bCol] = bReg;
        __syncthreads();
        if (kt + 1 < K / 8) {
            if (aAct) aReg = *(const float4*)(Ag + (kt + 1) * 8);
            if (bAct) bReg = *(const float4*)(Bg + (size_t)(kt + 1) * 8 * N);
        }
#pragma unroll
        for (int kk = 0; kk < 8; ++kk) {
            float4 a = *(const float4*)&As[kk][tm0];
            const float2* bp = (const float2*)&Bs[kk][tn0];
            float2 b01 = bp[0], b23 = bp[1], b45 = bp[2];
            float b[6] = {b01.x, b01.y, b23.x, b23.y, b45.x, b45.y};
            float av[4] = {a.x, a.y, a.z, a.w};
#pragma unroll
            for (int i = 0; i < 4; ++i)
#pragma unroll
                for (int j = 0; j < 6; ++j)
                    acc[i][j] += av[i] * b[j];
        }
        __syncthreads();
    }

    float bj[6];
#pragma unroll
    for (int j = 0; j < 6; ++j) bj[j] = bias[n0 + tn0 + j];
#pragma unroll
    for (int i = 0; i < 4; ++i) {
        int m = m0 + tm0 + i;
        int bb = m >> 11;
        int t  = m & 2047;
#pragma unroll
        for (int j = 0; j < 6; ++j) {
            int n = n0 + tn0 + j;
            float val = acc[i][j] + bj[j];
            int part = n >> 9;
            int r = n & 511;
            int h = r >> 6;
            int e = r & 63;
            size_t idx = (((size_t)(bb * Hq + h)) * Lq + t) * Eq + e;
            if (part == 0) {
                val = (val > 0.f ? val + 1.f : expf(val)) * 0.125f;
                g_q[idx] = val;
            } else if (part == 1) {
                val = (val > 0.f ? val + 1.f : expf(val));
                g_k[idx] = val;
            } else {
                g_v[idx] = val;
            }
        }
    }
}

// =================================================================
// GEMM2 (R14 verbatim — at floor): 32x64 tile, 64 threads, 8x4.
// =================================================================
__global__ __launch_bounds__(64)
void gemm_out_kernel(const float* __restrict__ W, const float* __restrict__ bias) {
    const int K = 512, N = 512;
    __shared__ __align__(16) float As[8][32];
    __shared__ __align__(16) float Bs[8][64];
    const int tid = threadIdx.x;
    const int m0 = blockIdx.y * 32;
    const int n0 = blockIdx.x * 64;

    const int aRow = tid >> 1;
    const int aCol = (tid & 1) << 2;
    const int bRow = tid >> 3;
    const int bCol = (tid & 7) << 3;

    const float* Ag = g_attn + (size_t)(m0 + aRow) * K + aCol;
    const float* Bg = W + (size_t)bRow * N + n0 + bCol;

    const int tm0 = (tid >> 4) << 3;
    const int tn0 = (tid & 15) << 2;

    float acc[8][4] = {};
    float4 aReg, bReg0, bReg1;
    aReg = *(const float4*)Ag;
    bReg0 = *(const float4*)Bg;
    bReg1 = *(const float4*)(Bg + 4);

    for (int kt = 0; kt < K / 8; ++kt) {
        As[aCol + 0][aRow] = aReg.x;
        As[aCol + 1][aRow] = aReg.y;
        As[aCol + 2][aRow] = aReg.z;
        As[aCol + 3][aRow] = aReg.w;
        *(float4*)&Bs[bRow][bCol] = bReg0;
        *(float4*)&Bs[bRow][bCol + 4] = bReg1;
        __syncthreads();
        if (kt + 1 < K / 8) {
            aReg = *(const float4*)(Ag + (kt + 1) * 8);
            bReg0 = *(const float4*)(Bg + (size_t)(kt + 1) * 8 * N);
            bReg1 = *(const float4*)(Bg + (size_t)(kt + 1) * 8 * N + 4);
        }
#pragma unroll
        for (int kk = 0; kk < 8; ++kk) {
            float4 a0 = *(const float4*)&As[kk][tm0];
            float4 a1 = *(const float4*)&As[kk][tm0 + 4];
            float4 b = *(const float4*)&Bs[kk][tn0];
            float av[8] = {a0.x, a0.y, a0.z, a0.w, a1.x, a1.y, a1.z, a1.w};
            float bv[4] = {b.x, b.y, b.z, b.w};
#pragma unroll
            for (int i = 0; i < 8; ++i)
#pragma unroll
                for (int j = 0; j < 4; ++j)
                    acc[i][j] += av[i] * bv[j];
        }
        __syncthreads();
    }

    float4 bb = *(const float4*)&bias[n0 + tn0];
#pragma unroll
    for (int i = 0; i < 8; ++i) {
        int m = m0 + tm0 + i;
        float4 v = make_float4(acc[i][0] + bb.x, acc[i][1] + bb.y,
                               acc[i][2] + bb.z, acc[i][3] + bb.w);
        *(float4*)(g_lin + (size_t)m * N + n0 + tn0) = v;
    }
}

// =================================================================
// K2: chunk summaries (R14 verbatim)
// =================================================================
__global__ __launch_bounds__(256)
void chunk_summary_kernel(const float* __restrict__ dlog) {
    __shared__ __align__(16) float Ks[4096];
    __shared__ __align__(16) float Vs[4096];
    __shared__ float lp[64];
    const int blk = blockIdx.x;
    const int bh = blk >> 5, c = blk & 31, h = bh & 7;
    const int tid = threadIdx.x;
    const float lam = 1.f / (1.f + expf(-dlog[h]));
    const float llog = logf(lam);
    const size_t off = ((size_t)bh * Lq + c * Cq) * Eq;
#pragma unroll
    for (int r = 0; r < 4; ++r) {
        int li = tid + 256 * r;
        ((float4*)Ks)[li] = ((const float4*)(g_k + off))[li];
        ((float4*)Vs)[li] = ((const float4*)(g_v + off))[li];
    }
    if (tid < 64) lp[tid] = expf((float)(63 - tid) * llog);
    __syncthreads();

    const int e = tid >> 2, f0 = (tid & 3) << 4;
    float acc[16] = {};
    float ks = 0.f;
    for (int j = 0; j < 64; ++j) {
        float kw = Ks[j * 64 + e] * lp[j];
        ks += kw;
#pragma unroll
        for (int ff = 0; ff < 16; ++ff) acc[ff] += kw * Vs[j * 64 + f0 + ff];
    }
    float* Mo = g_M + (size_t)blk * 4096 + e * 64 + f0;
#pragma unroll
    for (int ff = 0; ff < 16; ++ff) Mo[ff] = acc[ff];
    if ((tid & 3) == 0) g_ksum[blk * 64 + e] = ks;
}

// =================================================================
// K3: state scan with batched loads (MLP=8) to hide DRAM latency.
// 256 CTAs (16 bh x 16 groups), 1 state element/thread.
// =================================================================
__global__ __launch_bounds__(256)
void state_scan_kernel(const float* __restrict__ dlog) {
    const int bh = blockIdx.y;
    const int grp = blockIdx.x;
    const int tid = threadIdx.x;
    const int h = bh & 7;
    const float lam = 1.f / (1.f + expf(-dlog[h]));
    const float lamC = expf(64.f * logf(lam));
    const int eidx = grp * 256 + tid;
    const bool doPsum = (grp == 0) && (tid < 64);

    const size_t base0 = (size_t)bh * 32 * 4096 + eidx;
    float P = 0.f, ps = 0.f;
#pragma unroll
    for (int cb = 0; cb < 4; ++cb) {
        float m[8], kv[8];
#pragma unroll
        for (int u = 0; u < 8; ++u)
            m[u] = g_M[base0 + (size_t)(cb * 8 + u) * 4096];
        if (doPsum) {
#pragma unroll
            for (int u = 0; u < 8; ++u)
                kv[u] = g_ksum[(bh * 32 + cb * 8 + u) * 64 + tid];
        }
#pragma unroll
        for (int u = 0; u < 8; ++u) {
            int c = cb * 8 + u;
            g_P[base0 + (size_t)c * 4096] = P;
            P = lamC * P + m[u];
            if (doPsum) {
                g_psum[(bh * 32 + c) * 64 + tid] = ps;
                ps = lamC * ps + kv[u];
            }
        }
    }
}

// =================================================================
// K4 (R14 verbatim): per-chunk output, Aw aliases Ks, AV early exit.
// =================================================================
#define K4_SMEM_FLOATS (4 * 64 * 64 + 64 + 68)

__device__ __forceinline__ int ksw(int row, int col) {
    return row * 64 + ((((col >> 2) ^ ((row >> 2) & 15)) << 2) | (col & 3));
}

__global__ __launch_bounds__(256)
void chunk_output_kernel(const float* __restrict__ dlog) {
    extern __shared__ float sm[];
    float* Qs = sm;
    float* Ks = sm + 64 * 64;
    float* Vs = sm + 2 * 64 * 64;
    float* Ps = sm + 3 * 64 * 64;
    float* Aw = Ks;
    float* pv = sm + 4 * 64 * 64;
    float* lp = pv + 64;

    const int blk = blockIdx.x, bh = blk >> 5, c = blk & 31;
    const int h = bh & 7, b = bh >> 3;
    const int tid = threadIdx.x;
    const float lam = 1.f / (1.f + expf(-dlog[h]));
    const float llog = logf(lam);

    const size_t chunk_off = ((size_t)bh * Lq + c * Cq) * Eq;
    const float4* q4 = (const float4*)(g_q + chunk_off);
    const float4* k4 = (const float4*)(g_k + chunk_off);
    const float4* v4 = (const float4*)(g_v + chunk_off);
    const float4* p4 = (const float4*)(g_P + (size_t)blk * 4096);
#pragma unroll
    for (int r = 0; r < 4; ++r) {
        int li = tid + 256 * r;
        ((float4*)Qs)[li] = q4[li];
        ((float4*)Vs)[li] = v4[li];
        ((float4*)Ps)[li] = p4[li];
        int fe = li << 2;
        int row = fe >> 6, col = fe & 63;
        *(float4*)&Ks[ksw(row, col)] = k4[li];
    }
    if (tid < 64) pv[tid] = g_psum[blk * 64 + tid];
    if (tid < 65) lp[tid] = expf((float)tid * llog);
    __syncthreads();

    const int jb = (tid >> 4) << 2;
    const int fb = (tid & 15) << 2;

    float acc2[4][4] = {};
    for (int e0 = 0; e0 < 64; e0 += 4) {
        float4 qv[4], kv[4];
#pragma unroll
        for (int a = 0; a < 4; ++a) qv[a] = *(const float4*)&Qs[(jb + a) * 64 + e0];
#pragma unroll
        for (int d = 0; d < 4; ++d) kv[d] = *(const float4*)&Ks[ksw(fb + d, e0)];
#pragma unroll
        for (int a = 0; a < 4; ++a)
#pragma unroll
            for (int d = 0; d < 4; ++d)
                acc2[a][d] += qv[a].x * kv[d].x + qv[a].y * kv[d].y
                            + qv[a].z * kv[d].z + qv[a].w * kv[d].w;
    }
    __syncthreads();
#pragma unroll
    for (int a = 0; a < 4; ++a) {
        int j = jb + a;
        float4 w4;
        w4.x = (fb + 0 <= j) ? acc2[a][0] * lp[j - fb - 0] : 0.f;
        w4.y = (fb + 1 <= j) ? acc2[a][1] * lp[j - fb - 1] : 0.f;
        w4.z = (fb + 2 <= j) ? acc2[a][2] * lp[j - fb - 2] : 0.f;
        w4.w = (fb + 3 <= j) ? acc2[a][3] * lp[j - fb - 3] : 0.f;
        *(float4*)&Aw[j * 64 + fb] = w4;
    }
    __syncthreads();

    float4 o4[4] = {}, po4[4] = {};
    float dsum[4] = {}, dq[4] = {};
    for (int i0 = 0; i0 <= jb + 3; i0 += 4) {
        float4 av[4], vv[4];
#pragma unroll
        for (int a = 0; a < 4; ++a) av[a] = *(const float4*)&Aw[(jb + a) * 64 + i0];
#pragma unroll
        for (int d = 0; d < 4; ++d) vv[d] = *(const float4*)&Vs[(i0 + d) * 64 + fb];
#pragma unroll
        for (int a = 0; a < 4; ++a) {
            dsum[a] += av[a].x + av[a].y + av[a].z + av[a].w;
            o4[a].x += av[a].x * vv[0].x + av[a].y * vv[1].x + av[a].z * vv[2].x + av[a].w * vv[3].x;
            o4[a].y += av[a].x * vv[0].y + av[a].y * vv[1].y + av[a].z * vv[2].y + av[a].w * vv[3].y;
            o4[a].z += av[a].x * vv[0].z + av[a].y * vv[1].z + av[a].z * vv[2].z + av[a].w * vv[3].z;
            o4[a].w += av[a].x * vv[0].w + av[a].y * vv[1].w + av[a].z * vv[2].w + av[a].w * vv[3].w;
        }
    }
    for (int e0 = 0; e0 < 64; e0 += 4) {
        float4 qv[4], pw[4];
#pragma unroll
        for (int a = 0; a < 4; ++a) qv[a] = *(const float4*)&Qs[(jb + a) * 64 + e0];
#pragma unroll
        for (int d = 0; d < 4; ++d) pw[d] = *(const float4*)&Ps[(e0 + d) * 64 + fb];
        float4 pvv = *(const float4*)&pv[e0];
#pragma unroll
        for (int a = 0; a < 4; ++a) {
            dq[a] += qv[a].x * pvv.x + qv[a].y * pvv.y + qv[a].z * pvv.z + qv[a].w * pvv.w;
            po4[a].x += qv[a].x * pw[0].x + qv[a].y * pw[1].x + qv[a].z * pw[2].x + qv[a].w * pw[3].x;
            po4[a].y += qv[a].x * pw[0].y + qv[a].y * pw[1].y + qv[a].z * pw[2].y + qv[a].w * pw[3].y;
            po4[a].z += qv[a].x * pw[0].z + qv[a].y * pw[1].z + qv[a].z * pw[2].z + qv[a].w * pw[3].z;
            po4[a].w += qv[a].x * pw[0].w + qv[a].y * pw[1].w + qv[a].z * pw[2].w + qv[a].w * pw[3].w;
        }
    }

#pragma unroll
    for (int a = 0; a < 4; ++a) {
        int j = jb + a;
        float l1 = lp[j + 1];
        float inv = 1.f / (dsum[a] + l1 * dq[a] + 1e-5f);
        int t = c * Cq + j;
        float4 res;
        res.x = (o4[a].x + l1 * po4[a].x) * inv;
        res.y = (o4[a].y + l1 * po4[a].y) * inv;
        res.z = (o4[a].z + l1 * po4[a].z) * inv;
        res.w = (o4[a].w + l1 * po4[a].w) * inv;
        *(float4*)(g_attn + ((size_t)(b * Lq + t)) * Dq + h * Eq + fb) = res;
    }
}

// =================================================================
// K6: LayerNorm (R14 verbatim)
// =================================================================
__global__ __launch_bounds__(128)
void ln_kernel(const float* __restrict__ gamma, const float* __restrict__ beta,
               float* __restrict__ out) {
    const int row = blockIdx.x, tid = threadIdx.x;
    float4 v = ((const float4*)(g_lin + (size_t)row * Dq))[tid];
    float s = v.x + v.y + v.z + v.w;
    float ss = v.x * v.x + v.y * v.y + v.z * v.z + v.w * v.w;
#pragma unroll
    for (int o = 16; o; o >>= 1) {
        s  += __shfl_xor_sync(0xffffffffu, s, o);
        ss += __shfl_xor_sync(0xffffffffu, ss, o);
    }
    __shared__ float rs[4], rss[4];
    if ((tid & 31) == 0) { rs[tid >> 5] = s; rss[tid >> 5] = ss; }
    __syncthreads();
    s = rs[0] + rs[1] + rs[2] + rs[3];
    ss = rss[0] + rss[1] + rss[2] + rss[3];
    const float mean = s * (1.f / 512.f);
    const float var = ss * (1.f / 512.f) - mean * mean;
    const float inv = rsqrtf(var + 1e-5f);
    float4 g = ((const float4*)gamma)[tid];
    float4 be = ((const float4*)beta)[tid];
    float4 o4;
    o4.x = (v.x - mean) * inv * g.x + be.x;
    o4.y = (v.y - mean) * inv * g.y + be.y;
    o4.z = (v.z - mean) * inv * g.z + be.z;
    o4.w = (v.w - mean) * inv * g.w + be.w;
    ((float4*)(out + (size_t)row * Dq))[tid] = o4;
}

// =================================================================
extern "C" void kernel_launch(void* const* d_in, const int* in_sizes, int n_in,
                              void* d_out, int out_size) {
    const float* x     = (const float*)d_in[0];
    const float* Wqkv  = (const float*)d_in[1];
    const float* bqkv  = (const float*)d_in[2];
    const float* Wout  = (const float*)d_in[3];
    const float* bout  = (const float*)d_in[4];
    const float* gamma = (const float*)d_in[5];
    const float* beta  = (const float*)d_in[6];
    const float* dlog  = (const float*)d_in[7];
    float* out = (float*)d_out;

    cudaFuncSetAttribute(chunk_output_kernel,
                         cudaFuncAttributeMaxDynamicSharedMemorySize,
                         K4_SMEM_FLOATS * sizeof(float));

    gemm_qkv_kernel<<<dim3(16, 64), 256>>>(x, Wqkv, bqkv);

    chunk_summary_kernel<<<BHq * NCq, 256>>>(dlog);
    state_scan_kernel<<<dim3(16, 16), 256>>>(dlog);
    chunk_output_kernel<<<BHq * NCq, 256, K4_SMEM_FLOATS * sizeof(float)>>>(dlog);

    gemm_out_kernel<<<dim3(8, 128), 64>>>(Wout, bout);

    ln_kernel<<<Mrows, 128>>>(gamma, beta, out);
}

// round 17
// speedup vs baseline: 1.0536x; 1.0004x over previous
#include <cuda_runtime.h>
#include <cuda_bf16.h>
#include <math.h>

#define Bq   2
#define Lq   2048
#define Dq   512
#define Hq   8
#define Eq   64
#define Cq   64
#define NCq  (Lq / Cq)
#define BHq  (Bq * Hq)
#define Mrows (Bq * Lq)

// -------- scratch (device globals) --------
__device__ __align__(16) float g_q[BHq * Lq * Eq];
__device__ __align__(16) float g_k[BHq * Lq * Eq];
__device__ __align__(16) float g_v[BHq * Lq * Eq];
__device__ __align__(16) float g_M[BHq * NCq * Eq * Eq];
__device__ __align__(16) float g_P[BHq * NCq * Eq * Eq];
__device__ __align__(16) float g_ksum[BHq * NCq * Eq];
__device__ __align__(16) float g_psum[BHq * NCq * Eq];
__device__ __align__(16) float g_attn[Mrows * Dq];
__device__ __align__(16) float g_lin[Mrows * Dq];

// =================================================================
// GEMM1 (FROZEN): tile 64x96, 4x6, grid 16x64.
// =================================================================
__global__ __launch_bounds__(256)
void gemm_qkv_kernel(const float* __restrict__ X, const float* __restrict__ W,
                     const float* __restrict__ bias) {
    const int K = 512, N = 1536;
    __shared__ __align__(16) float As[8][64];
    __shared__ __align__(16) float Bs[8][96];
    const int tid = threadIdx.x;
    const int m0 = blockIdx.y * 64;
    const int n0 = blockIdx.x * 96;

    const bool aAct = tid < 128;
    const int aRow = tid >> 1;
    const int aCol = (tid & 1) << 2;
    const bool bAct = (tid & 31) < 24;
    const int bRow = tid >> 5;
    const int bCol = (tid & 31) << 2;

    const float* Ag = X + (size_t)(m0 + aRow) * K + aCol;
    const float* Bg = W + (size_t)bRow * N + n0 + bCol;

    const int tm0 = (tid & 15) << 2;
    const int tn0 = (tid >> 4) * 6;

    float acc[4][6] = {};
    float4 aReg, bReg;
    if (aAct) aReg = *(const float4*)Ag;
    if (bAct) bReg = *(const float4*)Bg;

    for (int kt = 0; kt < K / 8; ++kt) {
        if (aAct) {
            As[aCol + 0][aRow] = aReg.x;
            As[aCol + 1][aRow] = aReg.y;
            As[aCol + 2][aRow] = aReg.z;
            As[aCol + 3][aRow] = aReg.w;
        }
        if (bAct) *(float4*)&Bs[bRow][bCol] = bReg;
        __syncthreads();
        if (kt + 1 < K / 8) {
            if (aAct) aReg = *(const float4*)(Ag + (kt + 1) * 8);
            if (bAct) bReg = *(const float4*)(Bg + (size_t)(kt + 1) * 8 * N);
        }
#pragma unroll
        for (int kk = 0; kk < 8; ++kk) {
            float4 a = *(const float4*)&As[kk][tm0];
            const float2* bp = (const float2*)&Bs[kk][tn0];
            float2 b01 = bp[0], b23 = bp[1], b45 = bp[2];
            float b[6] = {b01.x, b01.y, b23.x, b23.y, b45.x, b45.y};
            float av[4] = {a.x, a.y, a.z, a.w};
#pragma unroll
            for (int i = 0; i < 4; ++i)
#pragma unroll
                for (int j = 0; j < 6; ++j)
                    acc[i][j] += av[i] * b[j];
        }
        __syncthreads();
    }

    float bj[6];
#pragma unroll
    for (int j = 0; j < 6; ++j) bj[j] = bias[n0 + tn0 + j];
#pragma unroll
    for (int i = 0; i < 4; ++i) {
        int m = m0 + tm0 + i;
        int bb = m >> 11;
        int t  = m & 2047;
#pragma unroll
        for (int j = 0; j < 6; ++j) {
            int n = n0 + tn0 + j;
            float val = acc[i][j] + bj[j];
            int part = n >> 9;
            int r = n & 511;
            int h = r >> 6;
            int e = r & 63;
            size_t idx = (((size_t)(bb * Hq + h)) * Lq + t) * Eq + e;
            if (part == 0) {
                val = (val > 0.f ? val + 1.f : expf(val)) * 0.125f;
                g_q[idx] = val;
            } else if (part == 1) {
                val = (val > 0.f ? val + 1.f : expf(val));
                g_k[idx] = val;
            } else {
                g_v[idx] = val;
            }
        }
    }
}

// =================================================================
// GEMM2 (FROZEN): 32x64 tile, 64 threads, 8x4, grid 8x128.
// =================================================================
__global__ __launch_bounds__(64)
void gemm_out_kernel(const float* __restrict__ W, const float* __restrict__ bias) {
    const int K = 512, N = 512;
    __shared__ __align__(16) float As[8][32];
    __shared__ __align__(16) float Bs[8][64];
    const int tid = threadIdx.x;
    const int m0 = blockIdx.y * 32;
    const int n0 = blockIdx.x * 64;

    const int aRow = tid >> 1;
    const int aCol = (tid & 1) << 2;
    const int bRow = tid >> 3;
    const int bCol = (tid & 7) << 3;

    const float* Ag = g_attn + (size_t)(m0 + aRow) * K + aCol;
    const float* Bg = W + (size_t)bRow * N + n0 + bCol;

    const int tm0 = (tid >> 4) << 3;
    const int tn0 = (tid & 15) << 2;

    float acc[8][4] = {};
    float4 aReg, bReg0, bReg1;
    aReg = *(const float4*)Ag;
    bReg0 = *(const float4*)Bg;
    bReg1 = *(const float4*)(Bg + 4);

    for (int kt = 0; kt < K / 8; ++kt) {
        As[aCol + 0][aRow] = aReg.x;
        As[aCol + 1][aRow] = aReg.y;
        As[aCol + 2][aRow] = aReg.z;
        As[aCol + 3][aRow] = aReg.w;
        *(float4*)&Bs[bRow][bCol] = bReg0;
        *(float4*)&Bs[bRow][bCol + 4] = bReg1;
        __syncthreads();
        if (kt + 1 < K / 8) {
            aReg = *(const float4*)(Ag + (kt + 1) * 8);
            bReg0 = *(const float4*)(Bg + (size_t)(kt + 1) * 8 * N);
            bReg1 = *(const float4*)(Bg + (size_t)(kt + 1) * 8 * N + 4);
        }
#pragma unroll
        for (int kk = 0; kk < 8; ++kk) {
            float4 a0 = *(const float4*)&As[kk][tm0];
            float4 a1 = *(const float4*)&As[kk][tm0 + 4];
            float4 b = *(const float4*)&Bs[kk][tn0];
            float av[8] = {a0.x, a0.y, a0.z, a0.w, a1.x, a1.y, a1.z, a1.w};
            float bv[4] = {b.x, b.y, b.z, b.w};
#pragma unroll
            for (int i = 0; i < 8; ++i)
#pragma unroll
                for (int j = 0; j < 4; ++j)
                    acc[i][j] += av[i] * bv[j];
        }
        __syncthreads();
    }

    float4 bb = *(const float4*)&bias[n0 + tn0];
#pragma unroll
    for (int i = 0; i < 8; ++i) {
        int m = m0 + tm0 + i;
        float4 v = make_float4(acc[i][0] + bb.x, acc[i][1] + bb.y,
                               acc[i][2] + bb.z, acc[i][3] + bb.w);
        *(float4*)(g_lin + (size_t)m * N + n0 + tn0) = v;
    }
}

// =================================================================
// K2: chunk summaries — float4 Vs loads + float4 accumulators.
// =================================================================
__global__ __launch_bounds__(256)
void chunk_summary_kernel(const float* __restrict__ dlog) {
    __shared__ __align__(16) float Ks[4096];
    __shared__ __align__(16) float Vs[4096];
    __shared__ float lp[64];
    const int blk = blockIdx.x;
    const int bh = blk >> 5, c = blk & 31, h = bh & 7;
    const int tid = threadIdx.x;
    const float lam = 1.f / (1.f + expf(-dlog[h]));
    const float llog = logf(lam);
    const size_t off = ((size_t)bh * Lq + c * Cq) * Eq;
#pragma unroll
    for (int r = 0; r < 4; ++r) {
        int li = tid + 256 * r;
        ((float4*)Ks)[li] = ((const float4*)(g_k + off))[li];
        ((float4*)Vs)[li] = ((const float4*)(g_v + off))[li];
    }
    if (tid < 64) lp[tid] = expf((float)(63 - tid) * llog);
    __syncthreads();

    const int e = tid >> 2, f0 = (tid & 3) << 4;
    float4 a0 = {}, a1 = {}, a2 = {}, a3 = {};
    float ks = 0.f;
#pragma unroll 2
    for (int j = 0; j < 64; ++j) {
        float kw = Ks[j * 64 + e] * lp[j];
        ks += kw;
        float4 v0 = *(const float4*)&Vs[j * 64 + f0];
        float4 v1 = *(const float4*)&Vs[j * 64 + f0 + 4];
        float4 v2 = *(const float4*)&Vs[j * 64 + f0 + 8];
        float4 v3 = *(const float4*)&Vs[j * 64 + f0 + 12];
        a0.x += kw * v0.x; a0.y += kw * v0.y; a0.z += kw * v0.z; a0.w += kw * v0.w;
        a1.x += kw * v1.x; a1.y += kw * v1.y; a1.z += kw * v1.z; a1.w += kw * v1.w;
        a2.x += kw * v2.x; a2.y += kw * v2.y; a2.z += kw * v2.z; a2.w += kw * v2.w;
        a3.x += kw * v3.x; a3.y += kw * v3.y; a3.z += kw * v3.z; a3.w += kw * v3.w;
    }
    float* Mo = g_M + (size_t)blk * 4096 + e * 64 + f0;
    *(float4*)(Mo + 0)  = a0;
    *(float4*)(Mo + 4)  = a1;
    *(float4*)(Mo + 8)  = a2;
    *(float4*)(Mo + 12) = a3;
    if ((tid & 3) == 0) g_ksum[blk * 64 + e] = ks;
}

// =================================================================
// K3 (R16 verbatim): batched-load state scan.
// =================================================================
__global__ __launch_bounds__(256)
void state_scan_kernel(const float* __restrict__ dlog) {
    const int bh = blockIdx.y;
    const int grp = blockIdx.x;
    const int tid = threadIdx.x;
    const int h = bh & 7;
    const float lam = 1.f / (1.f + expf(-dlog[h]));
    const float lamC = expf(64.f * logf(lam));
    const int eidx = grp * 256 + tid;
    const bool doPsum = (grp == 0) && (tid < 64);

    const size_t base0 = (size_t)bh * 32 * 4096 + eidx;
    float P = 0.f, ps = 0.f;
#pragma unroll
    for (int cb = 0; cb < 4; ++cb) {
        float m[8], kv[8];
#pragma unroll
        for (int u = 0; u < 8; ++u)
            m[u] = g_M[base0 + (size_t)(cb * 8 + u) * 4096];
        if (doPsum) {
#pragma unroll
            for (int u = 0; u < 8; ++u)
                kv[u] = g_ksum[(bh * 32 + cb * 8 + u) * 64 + tid];
        }
#pragma unroll
        for (int u = 0; u < 8; ++u) {
            int c = cb * 8 + u;
            g_P[base0 + (size_t)c * 4096] = P;
            P = lamC * P + m[u];
            if (doPsum) {
                g_psum[(bh * 32 + c) * 64 + tid] = ps;
                ps = lamC * ps + kv[u];
            }
        }
    }
}

// =================================================================
// K4: per-chunk output — fused QK^T + Q·P + dq loop (shared Qs loads).
// =================================================================
#define K4_SMEM_FLOATS (4 * 64 * 64 + 64 + 68)

__device__ __forceinline__ int ksw(int row, int col) {
    return row * 64 + ((((col >> 2) ^ ((row >> 2) & 15)) << 2) | (col & 3));
}

__global__ __launch_bounds__(256)
void chunk_output_kernel(const float* __restrict__ dlog) {
    extern __shared__ float sm[];
    float* Qs = sm;
    float* Ks = sm + 64 * 64;
    float* Vs = sm + 2 * 64 * 64;
    float* Ps = sm + 3 * 64 * 64;
    float* Aw = Ks;
    float* pv = sm + 4 * 64 * 64;
    float* lp = pv + 64;

    const int blk = blockIdx.x, bh = blk >> 5, c = blk & 31;
    const int h = bh & 7, b = bh >> 3;
    const int tid = threadIdx.x;
    const float lam = 1.f / (1.f + expf(-dlog[h]));
    const float llog = logf(lam);

    const size_t chunk_off = ((size_t)bh * Lq + c * Cq) * Eq;
    const float4* q4 = (const float4*)(g_q + chunk_off);
    const float4* k4 = (const float4*)(g_k + chunk_off);
    const float4* v4 = (const float4*)(g_v + chunk_off);
    const float4* p4 = (const float4*)(g_P + (size_t)blk * 4096);
#pragma unroll
    for (int r = 0; r < 4; ++r) {
        int li = tid + 256 * r;
        ((float4*)Qs)[li] = q4[li];
        ((float4*)Vs)[li] = v4[li];
        ((float4*)Ps)[li] = p4[li];
        int fe = li << 2;
        int row = fe >> 6, col = fe & 63;
        *(float4*)&Ks[ksw(row, col)] = k4[li];
    }
    if (tid < 64) pv[tid] = g_psum[blk * 64 + tid];
    if (tid < 65) lp[tid] = expf((float)tid * llog);
    __syncthreads();

    const int jb = (tid >> 4) << 2;
    const int fb = (tid & 15) << 2;

    // ---- Fused: QK^T (acc2), Q·P (po4), Q·psum (dq) — one Qs load set ----
    float acc2[4][4] = {};
    float4 po4[4] = {};
    float dq[4] = {};
    for (int e0 = 0; e0 < 64; e0 += 4) {
        float4 qv[4], kv[4], pw[4];
#pragma unroll
        for (int a = 0; a < 4; ++a) qv[a] = *(const float4*)&Qs[(jb + a) * 64 + e0];
#pragma unroll
        for (int d = 0; d < 4; ++d) kv[d] = *(const float4*)&Ks[ksw(fb + d, e0)];
#pragma unroll
        for (int d = 0; d < 4; ++d) pw[d] = *(const float4*)&Ps[(e0 + d) * 64 + fb];
        float4 pvv = *(const float4*)&pv[e0];
#pragma unroll
        for (int a = 0; a < 4; ++a) {
            dq[a] += qv[a].x * pvv.x + qv[a].y * pvv.y + qv[a].z * pvv.z + qv[a].w * pvv.w;
#pragma unroll
            for (int d = 0; d < 4; ++d)
                acc2[a][d] += qv[a].x * kv[d].x + qv[a].y * kv[d].y
                            + qv[a].z * kv[d].z + qv[a].w * kv[d].w;
            po4[a].x += qv[a].x * pw[0].x + qv[a].y * pw[1].x + qv[a].z * pw[2].x + qv[a].w * pw[3].x;
            po4[a].y += qv[a].x * pw[0].y + qv[a].y * pw[1].y + qv[a].z * pw[2].y + qv[a].w * pw[3].y;
            po4[a].z += qv[a].x * pw[0].z + qv[a].y * pw[1].z + qv[a].z * pw[2].z + qv[a].w * pw[3].z;
            po4[a].w += qv[a].x * pw[0].w + qv[a].y * pw[1].w + qv[a].z * pw[2].w + qv[a].w * pw[3].w;
        }
    }
    __syncthreads();
#pragma unroll
    for (int a = 0; a < 4; ++a) {
        int j = jb + a;
        float4 w4;
        w4.x = (fb + 0 <= j) ? acc2[a][0] * lp[j - fb - 0] : 0.f;
        w4.y = (fb + 1 <= j) ? acc2[a][1] * lp[j - fb - 1] : 0.f;
        w4.z = (fb + 2 <= j) ? acc2[a][2] * lp[j - fb - 2] : 0.f;
        w4.w = (fb + 3 <= j) ? acc2[a][3] * lp[j - fb - 3] : 0.f;
        *(float4*)&Aw[j * 64 + fb] = w4;
    }
    __syncthreads();

    // ---- AV with triangular early exit ----
    float4 o4[4] = {};
    float dsum[4] = {};
    for (int i0 = 0; i0 <= jb + 3; i0 += 4) {
        float4 av[4], vv[4];
#pragma unroll
        for (int a = 0; a < 4; ++a) av[a] = *(const float4*)&Aw[(jb + a) * 64 + i0];
#pragma unroll
        for (int d = 0; d < 4; ++d) vv[d] = *(const float4*)&Vs[(i0 + d) * 64 + fb];
#pragma unroll
        for (int a = 0; a < 4; ++a) {
            dsum[a] += av[a].x + av[a].y + av[a].z + av[a].w;
            o4[a].x += av[a].x * vv[0].x + av[a].y * vv[1].x + av[a].z * vv[2].x + av[a].w * vv[3].x;
            o4[a].y += av[a].x * vv[0].y + av[a].y * vv[1].y + av[a].z * vv[2].y + av[a].w * vv[3].y;
            o4[a].z += av[a].x * vv[0].z + av[a].y * vv[1].z + av[a].z * vv[2].z + av[a].w * vv[3].z;
            o4[a].w += av[a].x * vv[0].w + av[a].y * vv[1].w + av[a].z * vv[2].w + av[a].w * vv[3].w;
        }
    }

#pragma unroll
    for (int a = 0; a < 4; ++a) {
        int j = jb + a;
        float l1 = lp[j + 1];
        float inv = 1.f / (dsum[a] + l1 * dq[a] + 1e-5f);
        int t = c * Cq + j;
        float4 res;
        res.x = (o4[a].x + l1 * po4[a].x) * inv;
        res.y = (o4[a].y + l1 * po4[a].y) * inv;
        res.z = (o4[a].z + l1 * po4[a].z) * inv;
        res.w = (o4[a].w + l1 * po4[a].w) * inv;
        *(float4*)(g_attn + ((size_t)(b * Lq + t)) * Dq + h * Eq + fb) = res;
    }
}

// =================================================================
// K6: LayerNorm (verbatim)
// =================================================================
__global__ __launch_bounds__(128)
void ln_kernel(const float* __restrict__ gamma, const float* __restrict__ beta,
               float* __restrict__ out) {
    const int row = blockIdx.x, tid = threadIdx.x;
    float4 v = ((const float4*)(g_lin + (size_t)row * Dq))[tid];
    float s = v.x + v.y + v.z + v.w;
    float ss = v.x * v.x + v.y * v.y + v.z * v.z + v.w * v.w;
#pragma unroll
    for (int o = 16; o; o >>= 1) {
        s  += __shfl_xor_sync(0xffffffffu, s, o);
        ss += __shfl_xor_sync(0xffffffffu, ss, o);
    }
    __shared__ float rs[4], rss[4];
    if ((tid & 31) == 0) { rs[tid >> 5] = s; rss[tid >> 5] = ss; }
    __syncthreads();
    s = rs[0] + rs[1] + rs[2] + rs[3];
    ss = rss[0] + rss[1] + rss[2] + rss[3];
    const float mean = s * (1.f / 512.f);
    const float var = ss * (1.f / 512.f) - mean * mean;
    const float inv = rsqrtf(var + 1e-5f);
    float4 g = ((const float4*)gamma)[tid];
    float4 be = ((const float4*)beta)[tid];
    float4 o4;
    o4.x = (v.x - mean) * inv * g.x + be.x;
    o4.y = (v.y - mean) * inv * g.y + be.y;
    o4.z = (v.z - mean) * inv * g.z + be.z;
    o4.w = (v.w - mean) * inv * g.w + be.w;
    ((float4*)(out + (size_t)row * Dq))[tid] = o4;
}

// =================================================================
extern "C" void kernel_launch(void* const* d_in, const int* in_sizes, int n_in,
                              void* d_out, int out_size) {
    const float* x     = (const float*)d_in[0];
    const float* Wqkv  = (const float*)d_in[1];
    const float* bqkv  = (const float*)d_in[2];
    const float* Wout  = (const float*)d_in[3];
    const float* bout  = (const float*)d_in[4];
    const float* gamma = (const float*)d_in[5];
    const float* beta  = (const float*)d_in[6];
    const float* dlog  = (const float*)d_in[7];
    float* out = (float*)d_out;

    cudaFuncSetAttribute(chunk_output_kernel,
                         cudaFuncAttributeMaxDynamicSharedMemorySize,
                         K4_SMEM_FLOATS * sizeof(float));

    gemm_qkv_kernel<<<dim3(16, 64), 256>>>(x, Wqkv, bqkv);

    chunk_summary_kernel<<<BHq * NCq, 256>>>(dlog);
    state_scan_kernel<<<dim3(16, 16), 256>>>(dlog);
    chunk_output_kernel<<<BHq * NCq, 256, K4_SMEM_FLOATS * sizeof(float)>>>(dlog);

    gemm_out_kernel<<<dim3(8, 128), 64>>>(Wout, bout);

    ln_kernel<<<Mrows, 128>>>(gamma, beta, out);
}